// round 2
// baseline (speedup 1.0000x reference)
#include <cuda_runtime.h>

#define TT 20000
#define HID 150
#define LDP 160

// ---- scratch (static device globals; no allocation) ----
__device__ float g_Ha[(size_t)TT * LDP];   // states @ attn_W1
__device__ float g_Ps[(size_t)TT * LDP];   // states @ sc_W1[0:400]
__device__ float g_Pe[(size_t)TT * LDP];   // states @ sc_W1[400:800]
__device__ float g_PE[(size_t)TT * LDP];   // embeds @ sc_W1[800:1100]
__device__ float g_logit[TT];

struct GemmJobs {
    const float* A[4];
    const float* B[4];
    float*       C[4];
    int          K[4];
    int          lda[4];
};

// C[M,160] = A[M,K] @ B[K,150]  (cols 150..159 zero-padded)
// Tile: BM=128, BN=160 (full N), BK=8. 256 threads, 8x10 micro-tile.
__global__ __launch_bounds__(256, 2) void proj_gemm(GemmJobs jobs) {
    const int jid = blockIdx.y;
    const float* __restrict__ A = jobs.A[jid];
    const float* __restrict__ B = jobs.B[jid];
    float* __restrict__ C = jobs.C[jid];
    const int K = jobs.K[jid];
    const int lda = jobs.lda[jid];

    __shared__ float As[8][132];   // padded rows -> conflict-free, 16B-aligned (528B row)
    __shared__ float Bs[8][160];

    const int tid = threadIdx.x;
    const int tx = tid & 15;       // col group
    const int ty = tid >> 4;       // row group
    const int m0 = blockIdx.x * 128;

    float acc[8][10];
#pragma unroll
    for (int r = 0; r < 8; r++)
#pragma unroll
        for (int c = 0; c < 10; c++) acc[r][c] = 0.f;

    const int aRow = tid >> 1;
    const int aU = tid & 1;

    for (int k0 = 0; k0 < K; k0 += 8) {
        // stage global->regs
        float4 av = make_float4(0.f, 0.f, 0.f, 0.f);
        {
            int m = m0 + aRow;
            int kb = k0 + aU * 4;
            if (m < TT && kb < K) av = *(const float4*)(A + (size_t)m * lda + kb);
        }
        float bv[5];
#pragma unroll
        for (int i = 0; i < 5; i++) {
            int idx = tid + 256 * i;
            int kk = idx / 160;
            int j = idx - kk * 160;
            bv[i] = (k0 + kk < K && j < 150) ? B[(k0 + kk) * 150 + j] : 0.f;
        }
        __syncthreads();
        As[aU * 4 + 0][aRow] = av.x;
        As[aU * 4 + 1][aRow] = av.y;
        As[aU * 4 + 2][aRow] = av.z;
        As[aU * 4 + 3][aRow] = av.w;
#pragma unroll
        for (int i = 0; i < 5; i++) {
            int idx = tid + 256 * i;
            int kk = idx / 160;
            int j = idx - kk * 160;
            Bs[kk][j] = bv[i];
        }
        __syncthreads();
#pragma unroll
        for (int kk = 0; kk < 8; kk++) {
            float4 a0 = *(const float4*)&As[kk][ty * 8];
            float4 a1 = *(const float4*)&As[kk][ty * 8 + 4];
            float a[8] = {a0.x, a0.y, a0.z, a0.w, a1.x, a1.y, a1.z, a1.w};
            float b[10];
#pragma unroll
            for (int c = 0; c < 10; c++) b[c] = Bs[kk][tx + 16 * c];
#pragma unroll
            for (int r = 0; r < 8; r++)
#pragma unroll
                for (int c = 0; c < 10; c++) acc[r][c] = fmaf(a[r], b[c], acc[r][c]);
        }
    }
#pragma unroll
    for (int r = 0; r < 8; r++) {
        int m = m0 + ty * 8 + r;
        if (m < TT) {
#pragma unroll
            for (int c = 0; c < 10; c++) C[(size_t)m * LDP + tx + 16 * c] = acc[r][c];
        }
    }
}

// Attention MLP tail: logit[t] = relu(relu(Ha[t]+b1) @ W2 + b2) . W3 + b3
// 64 tokens per block, 512 threads; each warp: 4 tokens x (5 strided cols/lane).
__global__ __launch_bounds__(512) void attn_tail(
    const float* __restrict__ b1, const float* __restrict__ W2,
    const float* __restrict__ b2, const float* __restrict__ W3,
    const float* __restrict__ b3) {
    extern __shared__ float sm[];
    float* W2s = sm;              // 22512 (22500 + zero pad)
    float* W3s = W2s + 22512;     // 150
    float* b2s = W3s + 150;       // 150
    float* h1s = b2s + 150;       // 64*150 = 9600

    const int tid = threadIdx.x;
    for (int i = tid; i < 22500; i += 512) W2s[i] = W2[i];
    if (tid < 12) W2s[22500 + tid] = 0.f;
    if (tid < 150) { W3s[tid] = W3[tid]; b2s[tid] = b2[tid]; }

    const int t0 = blockIdx.x * 64;
    const int cnt = min(64, TT - t0);
    for (int idx = tid; idx < cnt * 150; idx += 512) {
        int t = idx / 150, k = idx - t * 150;
        float v = g_Ha[(size_t)(t0 + t) * LDP + k] + b1[k];
        h1s[idx] = fmaxf(v, 0.f);
    }
    __syncthreads();

    const int w = tid >> 5, lane = tid & 31;
    float acc[4][5];
#pragma unroll
    for (int i = 0; i < 4; i++)
#pragma unroll
        for (int c = 0; c < 5; c++) acc[i][c] = 0.f;

    for (int k = 0; k < 150; k++) {
        float bv[5];
#pragma unroll
        for (int c = 0; c < 5; c++) bv[c] = W2s[k * 150 + lane + 32 * c];
        float h[4];
#pragma unroll
        for (int i = 0; i < 4; i++) h[i] = h1s[(w * 4 + i) * 150 + k];
#pragma unroll
        for (int i = 0; i < 4; i++)
#pragma unroll
            for (int c = 0; c < 5; c++) acc[i][c] = fmaf(h[i], bv[c], acc[i][c]);
    }
#pragma unroll
    for (int i = 0; i < 4; i++) {
        float p = 0.f;
#pragma unroll
        for (int c = 0; c < 5; c++) {
            int j = lane + 32 * c;
            if (j < 150) p += fmaxf(acc[i][c] + b2s[j], 0.f) * W3s[j];
        }
#pragma unroll
        for (int off = 16; off > 0; off >>= 1) p += __shfl_xor_sync(0xffffffffu, p, off);
        int t = w * 4 + i;
        if (lane == 0 && t < cnt) g_logit[t0 + t] = p + b3[0];
    }
}

// Span scorer: persistent blocks over 64-span tiles (per width n).
// h1 = relu(Ps[s] + Pe[s+n-1] + sum_j w_j*PE[s+j] + b1), then 150x150 + dot(W3).
__global__ __launch_bounds__(512) void span_score(
    const float* __restrict__ b1, const float* __restrict__ W2,
    const float* __restrict__ b2, const float* __restrict__ W3,
    const float* __restrict__ b3, float* __restrict__ out, int totalTiles) {
    extern __shared__ float sm[];
    float* W2s = sm;               // 22512
    float* W3s = W2s + 22512;      // 150
    float* b2s = W3s + 150;        // 150
    float* b1s = b2s + 150;        // 150
    float* h1s = b1s + 150;        // 9600
    float* PEs = h1s + 9600;       // 73*150 = 10950
    float* ws  = PEs + 10950;      // 64*10 = 640

    const int tid = threadIdx.x;
    for (int i = tid; i < 22500; i += 512) W2s[i] = W2[i];
    if (tid < 12) W2s[22500 + tid] = 0.f;
    if (tid < 150) { W3s[tid] = W3[tid]; b2s[tid] = b2[tid]; b1s[tid] = b1[tid]; }
    const float bias3 = b3[0];
    const int w = tid >> 5, lane = tid & 31;

    for (int tile = blockIdx.x; tile < totalTiles; tile += gridDim.x) {
        // tile -> (n, s0)
        int n = 1, loc = tile;
#pragma unroll
        for (int nn = 1; nn <= 10; nn++) {
            int tn = (TT - nn + 1 + 63) >> 6;
            if (loc < tn) { n = nn; break; }
            loc -= tn;
        }
        const int s0 = loc << 6;
        const int S = TT - n + 1;
        const int cnt = min(64, S - s0);

        __syncthreads();  // protect previous tile's smem readers

        // stage PE rows [s0 .. s0+cnt+n-2]
        const int rows = cnt + n - 1;
        for (int idx = tid; idx < rows * 150; idx += 512) {
            int r = idx / 150, k = idx - r * 150;
            PEs[idx] = g_PE[(size_t)(s0 + r) * LDP + k];
        }
        // per-span softmax weights
        if (tid < cnt) {
            int s = s0 + tid;
            float l[10];
            float m = -1e30f;
            for (int j = 0; j < n; j++) { l[j] = g_logit[s + j]; m = fmaxf(m, l[j]); }
            float sum = 0.f;
            for (int j = 0; j < n; j++) { l[j] = expf(l[j] - m); sum += l[j]; }
            float inv = 1.f / sum;
            for (int j = 0; j < n; j++) ws[tid * 10 + j] = l[j] * inv;
        }
        __syncthreads();

        // h1 = relu(layer-1 pre-activation), built from projected pieces
        for (int idx = tid; idx < cnt * 150; idx += 512) {
            int t = idx / 150, k = idx - t * 150;
            int s = s0 + t;
            float a = g_Ps[(size_t)s * LDP + k] + g_Pe[(size_t)(s + n - 1) * LDP + k] + b1s[k];
            for (int j = 0; j < n; j++) a = fmaf(ws[t * 10 + j], PEs[(t + j) * 150 + k], a);
            h1s[idx] = fmaxf(a, 0.f);
        }
        __syncthreads();

        // layer 2 (150x150) + layer 3 (dot W3)
        float acc[4][5];
#pragma unroll
        for (int i = 0; i < 4; i++)
#pragma unroll
            for (int c = 0; c < 5; c++) acc[i][c] = 0.f;

        for (int k = 0; k < 150; k++) {
            float bv[5];
#pragma unroll
            for (int c = 0; c < 5; c++) bv[c] = W2s[k * 150 + lane + 32 * c];
            float h[4];
#pragma unroll
            for (int i = 0; i < 4; i++) h[i] = h1s[(w * 4 + i) * 150 + k];
#pragma unroll
            for (int i = 0; i < 4; i++)
#pragma unroll
                for (int c = 0; c < 5; c++) acc[i][c] = fmaf(h[i], bv[c], acc[i][c]);
        }
        const int base = (n - 1) * TT - ((n - 1) * (n - 2)) / 2;
#pragma unroll
        for (int i = 0; i < 4; i++) {
            float p = 0.f;
#pragma unroll
            for (int c = 0; c < 5; c++) {
                int j = lane + 32 * c;
                if (j < 150) p += fmaxf(acc[i][c] + b2s[j], 0.f) * W3s[j];
            }
#pragma unroll
            for (int off = 16; off > 0; off >>= 1) p += __shfl_xor_sync(0xffffffffu, p, off);
            int t = w * 4 + i;
            if (lane == 0 && t < cnt) out[base + s0 + t] = p + bias3;
        }
    }
}

extern "C" void kernel_launch(void* const* d_in, const int* in_sizes, int n_in,
                              void* d_out, int out_size) {
    const float* embeds  = (const float*)d_in[0];
    const float* states  = (const float*)d_in[1];
    const float* attn_W1 = (const float*)d_in[2];
    const float* attn_b1 = (const float*)d_in[3];
    const float* attn_W2 = (const float*)d_in[4];
    const float* attn_b2 = (const float*)d_in[5];
    const float* attn_W3 = (const float*)d_in[6];
    const float* attn_b3 = (const float*)d_in[7];
    const float* sc_W1   = (const float*)d_in[8];
    const float* sc_b1   = (const float*)d_in[9];
    const float* sc_W2   = (const float*)d_in[10];
    const float* sc_b2   = (const float*)d_in[11];
    const float* sc_W3   = (const float*)d_in[12];
    const float* sc_b3   = (const float*)d_in[13];
    float* out = (float*)d_out;

    float *pHa, *pPs, *pPe, *pPE;
    cudaGetSymbolAddress((void**)&pHa, g_Ha);
    cudaGetSymbolAddress((void**)&pPs, g_Ps);
    cudaGetSymbolAddress((void**)&pPe, g_Pe);
    cudaGetSymbolAddress((void**)&pPE, g_PE);

    GemmJobs jobs;
    jobs.A[0] = states; jobs.B[0] = attn_W1;            jobs.C[0] = pHa; jobs.K[0] = 400; jobs.lda[0] = 400;
    jobs.A[1] = states; jobs.B[1] = sc_W1;              jobs.C[1] = pPs; jobs.K[1] = 400; jobs.lda[1] = 400;
    jobs.A[2] = states; jobs.B[2] = sc_W1 + 400 * 150;  jobs.C[2] = pPe; jobs.K[2] = 400; jobs.lda[2] = 400;
    jobs.A[3] = embeds; jobs.B[3] = sc_W1 + 800 * 150;  jobs.C[3] = pPE; jobs.K[3] = 300; jobs.lda[3] = 300;

    const int attnSmem = (22512 + 150 + 150 + 9600) * 4;
    const int spanSmem = (22512 + 150 + 150 + 150 + 9600 + 10950 + 640) * 4;
    cudaFuncSetAttribute(attn_tail, cudaFuncAttributeMaxDynamicSharedMemorySize, attnSmem);
    cudaFuncSetAttribute(span_score, cudaFuncAttributeMaxDynamicSharedMemorySize, spanSmem);

    int totalTiles = 0;
    for (int nn = 1; nn <= 10; nn++) totalTiles += (TT - nn + 1 + 63) >> 6;

    proj_gemm<<<dim3((TT + 127) / 128, 4), 256>>>(jobs);
    attn_tail<<<(TT + 63) / 64, 512, attnSmem>>>(attn_b1, attn_W2, attn_b2, attn_W3, attn_b3);
    span_score<<<152, 512, spanSmem>>>(sc_b1, sc_W2, sc_b2, sc_W3, sc_b3, out, totalTiles);
}